// round 5
// baseline (speedup 1.0000x reference)
#include <cuda_runtime.h>
#include <math.h>
#include <stdint.h>

#define T_   256
#define B_   64
#define I_   256
#define H_   512
#define C_   64
#define G4H  2048
#define BH   (B_*H_)      // 32768
#define NCTA 136
#define NGEMM 128
#define NATT_CTA 8
#define NSYNC 256

// lstm smem layout (floats)
#define W2_STRIDE 1028            // 514 float2 per jp row (16B aligned, conflict-staggered)
#define H2_STRIDE 1024            // 512 dup'd float2 per b row
#define W2_ELE (32 * W2_STRIDE)   // 32896
#define H2_ELE (16 * H2_STRIDE)   // 16384
#define GS_ELE (16 * 68)          // 1088
#define SMEM_FLOATS (W2_ELE + H2_ELE + GS_ELE)
#define SMEM_BYTES  (SMEM_FLOATS * 4)   // ~201.5 KB

// ---------------- static device scratch ----------------
__device__ float    d_G[(size_t)T_ * B_ * G4H];
__device__ float    d_mem[(size_t)(T_ + 1) * BH];
__device__ float    d_mseq[(size_t)T_ * BH];
__device__ float    d_s2[B_ * (T_ + 1)];
__device__ unsigned d_bar[NSYNC];
__device__ unsigned d_aflag[NSYNC];

__device__ __forceinline__ float sigf(float x) { return 1.f / (1.f + __expf(-x)); }

// packed fp32x2 helpers (Blackwell FFMA2 path; only reachable via PTX)
__device__ __forceinline__ unsigned long long pk2(float x, float y) {
    unsigned long long r;
    asm("mov.b64 %0, {%1, %2};" : "=l"(r) : "f"(x), "f"(y));
    return r;
}
__device__ __forceinline__ void upk2(unsigned long long v, float& x, float& y) {
    asm("mov.b64 {%0, %1}, %2;" : "=f"(x), "=f"(y) : "l"(v));
}
__device__ __forceinline__ unsigned long long fma2(unsigned long long a,
                                                   unsigned long long b,
                                                   unsigned long long c) {
    unsigned long long d;
    asm("fma.rn.f32x2 %0, %1, %2, %3;" : "=l"(d) : "l"(a), "l"(b), "l"(c));
    return d;
}

__device__ __forceinline__ void gsync(int slot, unsigned nct) {
    __threadfence();
    __syncthreads();
    if (threadIdx.x == 0) {
        atomicAdd(&d_bar[slot], 1u);
        while (*((volatile unsigned*)&d_bar[slot]) < nct) { }
        __threadfence();
    }
    __syncthreads();
}

__global__ void noop_kernel() {}

// ---------------- reset ----------------
__global__ void reset_kernel() {
    int id = blockIdx.x * blockDim.x + threadIdx.x;   // 32768 threads
    d_mem[id] = 0.f;
    if (id < B_ * (T_ + 1)) d_s2[id] = 0.f;
    if (id < NSYNC) { d_bar[id] = 0u; d_aflag[id] = 0u; }
}

// ---------------- K1: G = x @ W_ih^T + (b_ih + b_hh), FFMA2 ----------------
// 64x64 tile, 256 threads, per-thread 4m x 4n (accs as 4x2 packed f32x2).
#define A2_STRIDE 132
__global__ void __launch_bounds__(256) gemm_ih_kernel(const float* __restrict__ X,
                                                      const float* __restrict__ Wih,
                                                      const float* __restrict__ bih,
                                                      const float* __restrict__ bhh) {
    __shared__ __align__(16) float a2f[16 * A2_STRIDE];   // [k][m-dup] 128+pad
    __shared__ __align__(16) float b_s[16][64];
    int tx = threadIdx.x;
    int m0 = blockIdx.y * 64, n0 = blockIdx.x * 64;
    int tm = tx & 15, tn = tx >> 4;
    unsigned long long acc[4][2];
#pragma unroll
    for (int r = 0; r < 4; r++) { acc[r][0] = 0ull; acc[r][1] = 0ull; }

    int row = tx >> 2, qd = tx & 3;
    for (int k0 = 0; k0 < I_; k0 += 16) {
        float4 av = *(const float4*)(X + (size_t)(m0 + row) * I_ + k0 + qd * 4);
        float4 bv = *(const float4*)(Wih + (size_t)(n0 + row) * I_ + k0 + qd * 4);
        // a: dup'd pairs a2f[k][2m],[2m+1] = (a,a)
        *(float2*)&a2f[(qd*4+0) * A2_STRIDE + 2*row] = make_float2(av.x, av.x);
        *(float2*)&a2f[(qd*4+1) * A2_STRIDE + 2*row] = make_float2(av.y, av.y);
        *(float2*)&a2f[(qd*4+2) * A2_STRIDE + 2*row] = make_float2(av.z, av.z);
        *(float2*)&a2f[(qd*4+3) * A2_STRIDE + 2*row] = make_float2(av.w, av.w);
        b_s[qd*4+0][row] = bv.x; b_s[qd*4+1][row] = bv.y;
        b_s[qd*4+2][row] = bv.z; b_s[qd*4+3][row] = bv.w;
        __syncthreads();
#pragma unroll
        for (int k = 0; k < 16; k++) {
            // 4 dup'd m values (32 B) + 2 n-pairs (16 B)
            ulonglong2 aA = *(const ulonglong2*)&a2f[k * A2_STRIDE + 8 * tm];
            ulonglong2 aB = *(const ulonglong2*)&a2f[k * A2_STRIDE + 8 * tm + 4];
            ulonglong2 bb = *(const ulonglong2*)&b_s[k][tn * 4];
            acc[0][0] = fma2(aA.x, bb.x, acc[0][0]); acc[0][1] = fma2(aA.x, bb.y, acc[0][1]);
            acc[1][0] = fma2(aA.y, bb.x, acc[1][0]); acc[1][1] = fma2(aA.y, bb.y, acc[1][1]);
            acc[2][0] = fma2(aB.x, bb.x, acc[2][0]); acc[2][1] = fma2(aB.x, bb.y, acc[2][1]);
            acc[3][0] = fma2(aB.y, bb.x, acc[3][0]); acc[3][1] = fma2(aB.y, bb.y, acc[3][1]);
        }
        __syncthreads();
    }
    float bias[4];
#pragma unroll
    for (int c = 0; c < 4; c++) {
        int n = n0 + tn * 4 + c;
        bias[c] = __ldg(bih + n) + __ldg(bhh + n);
    }
#pragma unroll
    for (int r = 0; r < 4; r++) {
        size_t m = (size_t)(m0 + tm * 4 + r);
        float4 o;
        upk2(acc[r][0], o.x, o.y);
        upk2(acc[r][1], o.z, o.w);
        o.x += bias[0]; o.y += bias[1]; o.z += bias[2]; o.w += bias[3];
        *(float4*)(d_G + m * G4H + n0 + tn * 4) = o;
    }
}

// ---------------- K2: fused persistent recurrent kernel (FFMA2 k-loop) ----------------
// CTAs 0..127: (jg=g>>2, bg=g&3). Tile 16 b x 16 h (64 gate cols). W2 persistent.
//   k-loop runs on warps 0..3 only (1/SMSP), thread tile 4b x 2j packed.
// CTAs 128..135: sparse attention, 1 warp/batch, flag handoff. One gsync/step.
__global__ void __launch_bounds__(256, 1) lstm_persistent(const float* __restrict__ W_hh,
                                                          const float* __restrict__ w_t) {
    extern __shared__ __align__(16) float smem[];
    float* w2f  = smem;                     // [jp][k] paired over j
    float* h2f  = smem + W2_ELE;            // [b][k] dup'd
    float* g_sm = smem + W2_ELE + H2_ELE;   // [bl][jj] stride 68

    int g = blockIdx.x, tx = threadIdx.x;
    int wrp = tx >> 5, lane = tx & 31;

    if (g < NGEMM) {
        int jg = g >> 2, bg = g & 3;
        int h0 = jg * 16;

        // ---- stage W2 once: w2f[jp*W2_STRIDE + 2k] = W[row(2jp)][k], +1 = W[row(2jp+1)][k]
#pragma unroll
        for (int q2 = 0; q2 < 64; q2++) {
            int idx = q2 * 256 + tx;             // [0, 16384)
            int jp = idx >> 9, k = idx & 511;
            int jj0 = 2 * jp, jj1 = 2 * jp + 1;
            int r0 = (jj0 >> 4) * H_ + h0 + (jj0 & 15);
            int r1 = (jj1 >> 4) * H_ + h0 + (jj1 & 15);
            float2 v;
            v.x = __ldg(W_hh + (size_t)r0 * H_ + k);
            v.y = __ldg(W_hh + (size_t)r1 * H_ + k);
            *(float2*)&w2f[jp * W2_STRIDE + 2 * k] = v;
        }
        __syncthreads();

        // k-warp mapping (warps 0..3, one per SMSP)
        int bq = lane >> 3;                  // 0..3 : b rows {bq, bq+4, bq+8, bq+12}
        int jq = lane & 7;
        int jp = wrp * 8 + jq;               // 0..31
        int jj0 = 2 * jp;
        size_t gcol = (size_t)(jj0 >> 4) * H_ + h0 + (jj0 & 15);

        // cell mapping (all 256 threads)
        int bl = tx >> 4, hi = tx & 15;
        float wt2v = __ldg(w_t + H_ + h0 + hi);
        float cstate = 0.f;

        for (int i = 0; i < T_; ++i) {
            // ---- prefetch acc init from d_G (overlaps h staging) ----
            unsigned long long acc[4];
            if (wrp < 4) {
#pragma unroll
                for (int r = 0; r < 4; r++) {
                    int b = bq + 4 * r;
                    float2 v = __ldcg((const float2*)(d_G +
                        ((size_t)i * B_ + bg * 16 + b) * G4H + gcol));
                    acc[r] = pk2(v.x, v.y);
                }
            }

            // ---- stage h2 (dup'd): h2f[b*1024 + 4*kp] = (h.x,h.x,h.y,h.y) ----
            const float* hrow = d_mem + (size_t)i * BH + (size_t)bg * 16 * H_;
#pragma unroll
            for (int q2 = 0; q2 < 16; q2++) {
                int it = q2 * 256 + tx;          // [0, 4096) float2 units
                int b = it >> 8, kp = it & 255;
                float2 v = __ldcg((const float2*)(hrow + (size_t)b * H_ + kp * 2));
                *(float4*)&h2f[b * H2_STRIDE + 4 * kp] = make_float4(v.x, v.x, v.y, v.y);
            }
            __syncthreads();

            // ---- k loop (warps 0..3): 2 k per iter ----
            if (wrp < 4) {
                const float* wb  = w2f + jp * W2_STRIDE;
                const float* hb0 = h2f + (bq + 0)  * H2_STRIDE;
                const float* hb1 = h2f + (bq + 4)  * H2_STRIDE;
                const float* hb2 = h2f + (bq + 8)  * H2_STRIDE;
                const float* hb3 = h2f + (bq + 12) * H2_STRIDE;
#pragma unroll 8
                for (int k2 = 0; k2 < H_; k2 += 2) {
                    ulonglong2 wv = *(const ulonglong2*)&wb[2 * k2];
                    ulonglong2 h0v = *(const ulonglong2*)&hb0[2 * k2];
                    ulonglong2 h1v = *(const ulonglong2*)&hb1[2 * k2];
                    ulonglong2 h2v = *(const ulonglong2*)&hb2[2 * k2];
                    ulonglong2 h3v = *(const ulonglong2*)&hb3[2 * k2];
                    acc[0] = fma2(h0v.x, wv.x, acc[0]);
                    acc[1] = fma2(h1v.x, wv.x, acc[1]);
                    acc[2] = fma2(h2v.x, wv.x, acc[2]);
                    acc[3] = fma2(h3v.x, wv.x, acc[3]);
                    acc[0] = fma2(h0v.y, wv.y, acc[0]);
                    acc[1] = fma2(h1v.y, wv.y, acc[1]);
                    acc[2] = fma2(h2v.y, wv.y, acc[2]);
                    acc[3] = fma2(h3v.y, wv.y, acc[3]);
                }
                // stage gates to smem: g_sm[b][jj0..jj0+1]
                float gx, gy;
#pragma unroll
                for (int r = 0; r < 4; r++) {
                    int b = bq + 4 * r;
                    upk2(acc[r], gx, gy);
                    *(float2*)&g_sm[b * 68 + jj0] = make_float2(gx, gy);
                }
            }

            // ---- wait for attention m_t ----
            if (tx == 0) {
                volatile unsigned* fl = (volatile unsigned*)d_aflag;
                while (fl[i] < (unsigned)NATT_CTA) { }
            }
            __syncthreads();

            // ---- LSTM cell: (b = bg*16+bl, h = h0+hi) ----
            {
                float gi = g_sm[bl * 68 + hi];
                float gf = g_sm[bl * 68 + 16 + hi];
                float gg = g_sm[bl * 68 + 32 + hi];
                float go = g_sm[bl * 68 + 48 + hi];
                size_t off = (size_t)(bg * 16 + bl) * H_ + h0 + hi;
                float mt = __ldcg(d_mseq + (size_t)i * BH + off);

                float cn = sigf(gf) * cstate + sigf(gi) * tanhf(gg);
                float hn = sigf(go) * tanhf(cn);
                cstate = cn;
                float ho = hn + mt;

                d_mem[(size_t)(i + 1) * BH + off] = ho;

                float part = tanhf(ho) * wt2v;
#pragma unroll
                for (int o = 8; o > 0; o >>= 1) part += __shfl_xor_sync(0xffffffffu, part, o);
                if ((lane & 15) == 0)
                    atomicAdd(&d_s2[(bg * 16 + bl) * (T_ + 1) + (i + 1)], part);
            }

            gsync(i, NCTA);
        }
    } else {
        // ---------------- attention CTAs ----------------
        int b = (g - NGEMM) * 8 + wrp;
        for (int i = 0; i < T_; ++i) {
            int n = i + 1;
            float v[8];
            float mn = INFINITY;
#pragma unroll
            for (int r = 0; r < 8; r++) {
                int t = lane + 32 * r;
                if (t < n) {
                    float s = __ldcg(d_s2 + b * (T_ + 1) + t);
                    v[r] = s;
                    mn = fminf(mn, s);
                } else {
                    v[r] = -INFINITY;
                }
            }
#pragma unroll
            for (int o = 16; o > 0; o >>= 1) mn = fminf(mn, __shfl_xor_sync(0xffffffffu, mn, o));
            float topv[5]; int topt[5];
#pragma unroll
            for (int k5 = 0; k5 < 5; k5++) {
                float bv = -INFINITY; int bt = 1 << 30;
#pragma unroll
                for (int r = 0; r < 8; r++) {
                    int t = lane + 32 * r;
                    if (v[r] > bv) { bv = v[r]; bt = t; }
                }
#pragma unroll
                for (int o = 16; o > 0; o >>= 1) {
                    float ov = __shfl_xor_sync(0xffffffffu, bv, o);
                    int   ot = __shfl_xor_sync(0xffffffffu, bt, o);
                    if (ov > bv || (ov == bv && ot < bt)) { bv = ov; bt = ot; }
                }
                topv[k5] = bv; topt[k5] = bt;
                int rr = bt >> 5;
                if ((bt & 31) == lane && rr >= 0 && rr < 8) v[rr] = -INFINITY;
            }
            float delta = ((n <= 5) ? mn : topv[4]) + 1e-7f;
            float wk[5]; float sum = 0.f;
#pragma unroll
            for (int k5 = 0; k5 < 5; k5++) { wk[k5] = fmaxf(topv[k5] - delta, 0.f); sum += wk[k5]; }
            float inv = 1.f / (sum + 1e-7f);
            float acc[16];
#pragma unroll
            for (int r = 0; r < 16; r++) acc[r] = 0.f;
#pragma unroll
            for (int k5 = 0; k5 < 5; k5++) {
                float wv = wk[k5] * inv;
                if (wv > 0.f) {
                    const float* rowp = d_mem + (size_t)topt[k5] * BH + (size_t)b * H_;
#pragma unroll
                    for (int r = 0; r < 16; r++) acc[r] = fmaf(wv, __ldg(rowp + lane + 32 * r), acc[r]);
                }
            }
            float* mrow = d_mseq + (size_t)i * BH + (size_t)b * H_;
#pragma unroll
            for (int r = 0; r < 16; r++) mrow[lane + 32 * r] = acc[r];

            __threadfence();
            __syncthreads();
            if (tx == 0) atomicAdd(&d_aflag[i], 1u);

            gsync(i, NCTA);
        }
    }
}

// ---------------- K3: out = [h_seq | m_seq] @ fc_w^T + fc_b ----------------
__global__ void __launch_bounds__(256) fc_final_kernel(const float* __restrict__ fcw,
                                                       const float* __restrict__ fcb,
                                                       float* __restrict__ out) {
    __shared__ __align__(16) float a_s[16][64];
    __shared__ __align__(16) float b_s[16][64];
    int tx = threadIdx.x;
    int m0 = blockIdx.x * 64;
    int tm = tx & 15, tn = tx >> 4;
    float acc[4][4];
#pragma unroll
    for (int r = 0; r < 4; r++)
#pragma unroll
        for (int c = 0; c < 4; c++) acc[r][c] = 0.f;

    int row = tx >> 2, qd = tx & 3;
    int m = m0 + row, t = m >> 6, b = m & 63;
    for (int k0 = 0; k0 < 2 * H_; k0 += 16) {
        int k = k0 + qd * 4;
        const float* src = (k < H_)
            ? (d_mem + ((size_t)(t + 1) * B_ + b) * H_ + k)
            : (d_mseq + ((size_t)t * B_ + b) * H_ + (k - H_));
        float4 av = *(const float4*)src;
        float4 bv = *(const float4*)(fcw + (size_t)row * (2 * H_) + k);
        a_s[qd*4+0][row] = av.x; a_s[qd*4+1][row] = av.y; a_s[qd*4+2][row] = av.z; a_s[qd*4+3][row] = av.w;
        b_s[qd*4+0][row] = bv.x; b_s[qd*4+1][row] = bv.y; b_s[qd*4+2][row] = bv.z; b_s[qd*4+3][row] = bv.w;
        __syncthreads();
#pragma unroll
        for (int k2 = 0; k2 < 16; k2++) {
            float4 a = *(const float4*)&a_s[k2][tm * 4];
            float4 bb = *(const float4*)&b_s[k2][tn * 4];
            acc[0][0] = fmaf(a.x, bb.x, acc[0][0]); acc[0][1] = fmaf(a.x, bb.y, acc[0][1]);
            acc[0][2] = fmaf(a.x, bb.z, acc[0][2]); acc[0][3] = fmaf(a.x, bb.w, acc[0][3]);
            acc[1][0] = fmaf(a.y, bb.x, acc[1][0]); acc[1][1] = fmaf(a.y, bb.y, acc[1][1]);
            acc[1][2] = fmaf(a.y, bb.z, acc[1][2]); acc[1][3] = fmaf(a.y, bb.w, acc[1][3]);
            acc[2][0] = fmaf(a.z, bb.x, acc[2][0]); acc[2][1] = fmaf(a.z, bb.y, acc[2][1]);
            acc[2][2] = fmaf(a.z, bb.z, acc[2][2]); acc[2][3] = fmaf(a.z, bb.w, acc[2][3]);
            acc[3][0] = fmaf(a.w, bb.x, acc[3][0]); acc[3][1] = fmaf(a.w, bb.y, acc[3][1]);
            acc[3][2] = fmaf(a.w, bb.z, acc[3][2]); acc[3][3] = fmaf(a.w, bb.w, acc[3][3]);
        }
        __syncthreads();
    }
    float bias[4];
#pragma unroll
    for (int c = 0; c < 4; c++) bias[c] = __ldg(fcb + tn * 4 + c);
#pragma unroll
    for (int r = 0; r < 4; r++) {
        size_t mm = (size_t)(m0 + tm * 4 + r);
        float4 o;
        o.x = acc[r][0] + bias[0]; o.y = acc[r][1] + bias[1];
        o.z = acc[r][2] + bias[2]; o.w = acc[r][3] + bias[3];
        *(float4*)(out + mm * C_ + tn * 4) = o;
    }
}

// ---------------- launch ----------------
extern "C" void kernel_launch(void* const* d_in, const int* in_sizes, int n_in,
                              void* d_out, int out_size) {
    const float* x    = (const float*)d_in[0];
    const float* W_ih = (const float*)d_in[1];
    const float* W_hh = (const float*)d_in[2];
    const float* b_ih = (const float*)d_in[3];
    const float* b_hh = (const float*)d_in[4];
    const float* w_t  = (const float*)d_in[5];
    const float* fc_w = (const float*)d_in[6];
    const float* fc_b = (const float*)d_in[7];
    float* out = (float*)d_out;

    static int smem_set = 0;
    if (!smem_set) {
        cudaFuncSetAttribute(lstm_persistent,
                             cudaFuncAttributeMaxDynamicSharedMemorySize, SMEM_BYTES);
        smem_set = 1;
    }

    // 3 no-op launches: shifts lstm_persistent to launch #6 so ncu (-s 5 -c 1)
    // finally profiles the dominant kernel.
    noop_kernel<<<1, 1>>>();
    noop_kernel<<<1, 1>>>();
    noop_kernel<<<1, 1>>>();
    reset_kernel<<<64, 512>>>();
    gemm_ih_kernel<<<dim3(G4H / 64, (T_ * B_) / 64), 256>>>(x, W_ih, b_ih, b_hh);
    lstm_persistent<<<NCTA, 256, SMEM_BYTES>>>(W_hh, w_t);
    fc_final_kernel<<<(T_ * B_) / 64, 256>>>(fc_w, fc_b, out);
}

// round 6
// speedup vs baseline: 1.5570x; 1.5570x over previous
#include <cuda_runtime.h>
#include <math.h>
#include <stdint.h>

#define T_   256
#define B_   64
#define I_   256
#define H_   512
#define C_   64
#define G4H  2048
#define BH   (B_*H_)      // 32768
#define NCTA 136
#define NGEMM 128
#define NATT_CTA 8
#define NSYNC 256

// lstm smem (floats): w2 [k][jp-pairs] stride 68, h2dup [k][b-dup] stride 36,
// partials [kg][b][j] 4*1024. g_sm (16x68) aliases h2 start.
#define W2S 68
#define H2S 36
#define W2_ELE (512 * W2S)        // 34816
#define H2_ELE (512 * H2S)        // 18432
#define PT_ELE (4 * 1024)         // 4096
#define SMEM_FLOATS (W2_ELE + H2_ELE + PT_ELE)
#define SMEM_BYTES  (SMEM_FLOATS * 4)   // 229376 B

// ---------------- static device scratch ----------------
__device__ float    d_G[(size_t)T_ * B_ * G4H];
__device__ float    d_mem[(size_t)(T_ + 1) * BH];
__device__ float    d_mseq[(size_t)T_ * BH];
__device__ float    d_s2[B_ * (T_ + 1)];
__device__ unsigned d_bar[NSYNC];
__device__ unsigned d_aflag[NSYNC];

__device__ __forceinline__ float sigf(float x) { return 1.f / (1.f + __expf(-x)); }

__device__ __forceinline__ void upk2(unsigned long long v, float& x, float& y) {
    asm("mov.b64 {%0, %1}, %2;" : "=f"(x), "=f"(y) : "l"(v));
}
__device__ __forceinline__ unsigned long long fma2(unsigned long long a,
                                                   unsigned long long b,
                                                   unsigned long long c) {
    unsigned long long d;
    asm("fma.rn.f32x2 %0, %1, %2, %3;" : "=l"(d) : "l"(a), "l"(b), "l"(c));
    return d;
}

__device__ __forceinline__ void gsync(int slot, unsigned nct) {
    __threadfence();
    __syncthreads();
    if (threadIdx.x == 0) {
        atomicAdd(&d_bar[slot], 1u);
        while (*((volatile unsigned*)&d_bar[slot]) < nct) { }
        __threadfence();
    }
    __syncthreads();
}

__global__ void noop_kernel() {}

// ---------------- reset ----------------
__global__ void reset_kernel() {
    int id = blockIdx.x * blockDim.x + threadIdx.x;   // 32768 threads
    d_mem[id] = 0.f;
    if (id < B_ * (T_ + 1)) d_s2[id] = 0.f;
    if (id < NSYNC) { d_bar[id] = 0u; d_aflag[id] = 0u; }
}

// ---------------- K1: G = x @ W_ih^T + (b_ih + b_hh) (R3 scalar version) ----------------
__global__ void __launch_bounds__(256) gemm_ih_kernel(const float* __restrict__ X,
                                                      const float* __restrict__ Wih,
                                                      const float* __restrict__ bih,
                                                      const float* __restrict__ bhh) {
    __shared__ __align__(16) float a_s[16][64];
    __shared__ __align__(16) float b_s[16][64];
    int tx = threadIdx.x;
    int m0 = blockIdx.y * 64, n0 = blockIdx.x * 64;
    int tm = tx & 15, tn = tx >> 4;
    float acc[4][4];
#pragma unroll
    for (int r = 0; r < 4; r++)
#pragma unroll
        for (int c = 0; c < 4; c++) acc[r][c] = 0.f;

    int row = tx >> 2, qd = tx & 3;
    for (int k0 = 0; k0 < I_; k0 += 16) {
        float4 av = *(const float4*)(X + (size_t)(m0 + row) * I_ + k0 + qd * 4);
        float4 bv = *(const float4*)(Wih + (size_t)(n0 + row) * I_ + k0 + qd * 4);
        a_s[qd*4+0][row] = av.x; a_s[qd*4+1][row] = av.y; a_s[qd*4+2][row] = av.z; a_s[qd*4+3][row] = av.w;
        b_s[qd*4+0][row] = bv.x; b_s[qd*4+1][row] = bv.y; b_s[qd*4+2][row] = bv.z; b_s[qd*4+3][row] = bv.w;
        __syncthreads();
#pragma unroll
        for (int k = 0; k < 16; k++) {
            float4 a = *(const float4*)&a_s[k][tm * 4];
            float4 b = *(const float4*)&b_s[k][tn * 4];
            acc[0][0] = fmaf(a.x, b.x, acc[0][0]); acc[0][1] = fmaf(a.x, b.y, acc[0][1]);
            acc[0][2] = fmaf(a.x, b.z, acc[0][2]); acc[0][3] = fmaf(a.x, b.w, acc[0][3]);
            acc[1][0] = fmaf(a.y, b.x, acc[1][0]); acc[1][1] = fmaf(a.y, b.y, acc[1][1]);
            acc[1][2] = fmaf(a.y, b.z, acc[1][2]); acc[1][3] = fmaf(a.y, b.w, acc[1][3]);
            acc[2][0] = fmaf(a.z, b.x, acc[2][0]); acc[2][1] = fmaf(a.z, b.y, acc[2][1]);
            acc[2][2] = fmaf(a.z, b.z, acc[2][2]); acc[2][3] = fmaf(a.z, b.w, acc[2][3]);
            acc[3][0] = fmaf(a.w, b.x, acc[3][0]); acc[3][1] = fmaf(a.w, b.y, acc[3][1]);
            acc[3][2] = fmaf(a.w, b.z, acc[3][2]); acc[3][3] = fmaf(a.w, b.w, acc[3][3]);
        }
        __syncthreads();
    }
    float bias[4];
#pragma unroll
    for (int c = 0; c < 4; c++) {
        int n = n0 + tn * 4 + c;
        bias[c] = __ldg(bih + n) + __ldg(bhh + n);
    }
#pragma unroll
    for (int r = 0; r < 4; r++) {
        size_t m = (size_t)(m0 + tm * 4 + r);
        float4 o;
        o.x = acc[r][0] + bias[0]; o.y = acc[r][1] + bias[1];
        o.z = acc[r][2] + bias[2]; o.w = acc[r][3] + bias[3];
        *(float4*)(d_G + m * G4H + n0 + tn * 4) = o;
    }
}

// ---------------- K2: fused persistent recurrent kernel ----------------
// GEMM CTAs: 8 warps = 4 k-groups x 2 b-halves; FFMA2 k-loop into partials; smem reduce;
// in-register LSTM cell. Attention CTAs: 1 warp/batch; flag handoff. One gsync/step.
__global__ void __launch_bounds__(256, 1) lstm_persistent(const float* __restrict__ W_hh,
                                                          const float* __restrict__ w_t) {
    extern __shared__ __align__(16) float smem[];
    float* w2f  = smem;                     // [k][2*jp] pairs, stride W2S
    float* h2f  = smem + W2_ELE;            // [k][2*b] dup'd pairs, stride H2S
    float* p_sm = smem + W2_ELE + H2_ELE;   // partials [kg][b][j]
    float* g_sm = h2f;                      // gates [b][j] stride 68 (aliases h2, safe by sync order)

    int g = blockIdx.x, tx = threadIdx.x;
    int wrp = tx >> 5, lane = tx & 31;

    if (g < NGEMM) {
        int jg = g >> 2, bg = g & 3;
        int h0 = jg * 16;

        // ---- stage W pairs once: w2f[k*W2S + 2*jp] = (W[row(2jp)][k], W[row(2jp+1)][k])
#pragma unroll
        for (int q2 = 0; q2 < 64; q2++) {
            int idx = q2 * 256 + tx;             // [0, 16384)
            int jp = idx >> 9, k = idx & 511;
            int jj0 = 2 * jp, jj1 = 2 * jp + 1;
            int r0 = (jj0 >> 4) * H_ + h0 + (jj0 & 15);
            int r1 = (jj1 >> 4) * H_ + h0 + (jj1 & 15);
            float2 v;
            v.x = __ldg(W_hh + (size_t)r0 * H_ + k);
            v.y = __ldg(W_hh + (size_t)r1 * H_ + k);
            *(float2*)&w2f[k * W2S + 2 * jp] = v;
        }
        __syncthreads();

        // k-loop mapping: all 8 warps
        int kg = wrp & 3, half = wrp >> 2;
        int bq = lane >> 3, jq = lane & 7;
        int b0 = half * 8 + bq * 2;              // even; covers b0, b0+1

        // reduce/cell mapping
        int bl = tx >> 4;                        // b in [0,16)
        int j0 = (tx & 15) * 4;                  // 4 consecutive jj
        int hi = tx & 15;
        const float* gsrc = d_G + ((size_t)bg * 16 + bl) * G4H
                            + (size_t)(j0 >> 4) * H_ + h0 + (j0 & 15);
        float wt2v = __ldg(w_t + H_ + h0 + hi);
        float cstate = 0.f;

        for (int i = 0; i < T_; ++i) {
            // ---- prefetch input-proj gates for this thread's reduce slice ----
            float4 gpre = __ldcg((const float4*)(gsrc + (size_t)i * B_ * G4H));

            // ---- stage h2 dup'd: h2f[k*H2S + 2b] = (h,h) ----
            const float* hrow = d_mem + (size_t)i * BH + (size_t)bg * 16 * H_;
#pragma unroll
            for (int q2 = 0; q2 < 8; q2++) {
                int it = q2 * 256 + tx;          // [0,2048)
                int b = it & 15, kq = it >> 4;   // kq in [0,128) -> k = 4kq..4kq+3
                float4 v = __ldcg((const float4*)(hrow + (size_t)b * H_ + kq * 4));
                *(float2*)&h2f[(4*kq+0) * H2S + 2*b] = make_float2(v.x, v.x);
                *(float2*)&h2f[(4*kq+1) * H2S + 2*b] = make_float2(v.y, v.y);
                *(float2*)&h2f[(4*kq+2) * H2S + 2*b] = make_float2(v.z, v.z);
                *(float2*)&h2f[(4*kq+3) * H2S + 2*b] = make_float2(v.w, v.w);
            }
            __syncthreads();

            // ---- FFMA2 k-loop: 128 k per warp ----
            {
                unsigned long long a0=0,a1=0,a2=0,a3=0,a4=0,a5=0,a6=0,a7=0;
                const float* wp = w2f + (size_t)(kg * 128) * W2S + 4 * jq;
                const float* hp = h2f + (size_t)(kg * 128) * H2S + 2 * b0;
#pragma unroll 8
                for (int k = 0; k < 128; k++) {
                    ulonglong2 hv = *(const ulonglong2*)hp;        // (h0,h0),(h1,h1)
                    ulonglong2 wA = *(const ulonglong2*)wp;        // jpairs 2jq, 2jq+1
                    ulonglong2 wB = *(const ulonglong2*)(wp + 32); // jpairs 16+2jq, 17+2jq
                    a0 = fma2(hv.x, wA.x, a0); a1 = fma2(hv.x, wA.y, a1);
                    a2 = fma2(hv.x, wB.x, a2); a3 = fma2(hv.x, wB.y, a3);
                    a4 = fma2(hv.y, wA.x, a4); a5 = fma2(hv.y, wA.y, a5);
                    a6 = fma2(hv.y, wB.x, a6); a7 = fma2(hv.y, wB.y, a7);
                    wp += W2S; hp += H2S;
                }
                // store partials: p_sm[kg*1024 + b*64 + j]
                float* pb = p_sm + kg * 1024 + b0 * 64 + 4 * jq;
                float4 o; 
                upk2(a0, o.x, o.y); upk2(a1, o.z, o.w); *(float4*)pb = o;
                upk2(a2, o.x, o.y); upk2(a3, o.z, o.w); *(float4*)(pb + 32) = o;
                upk2(a4, o.x, o.y); upk2(a5, o.z, o.w); *(float4*)(pb + 64) = o;
                upk2(a6, o.x, o.y); upk2(a7, o.z, o.w); *(float4*)(pb + 96) = o;
            }

            // ---- wait for attention m_t of this step ----
            if (tx == 0) {
                volatile unsigned* fl = (volatile unsigned*)d_aflag;
                while (fl[i] < (unsigned)NATT_CTA) { }
            }
            __syncthreads();   // partials complete + flag visible

            // ---- reduce 4 partials + input proj -> g_sm ----
            {
                float4 s = gpre;
#pragma unroll
                for (int kk = 0; kk < 4; kk++) {
                    float4 p = *(const float4*)&p_sm[kk * 1024 + bl * 64 + j0];
                    s.x += p.x; s.y += p.y; s.z += p.z; s.w += p.w;
                }
                *(float4*)&g_sm[bl * 68 + j0] = s;
            }
            __syncthreads();

            // ---- LSTM cell: (b = bg*16+bl, h = h0+hi) ----
            {
                float gi = g_sm[bl * 68 + hi];
                float gf = g_sm[bl * 68 + 16 + hi];
                float gg = g_sm[bl * 68 + 32 + hi];
                float go = g_sm[bl * 68 + 48 + hi];
                size_t off = (size_t)(bg * 16 + bl) * H_ + h0 + hi;
                float mt = __ldcg(d_mseq + (size_t)i * BH + off);

                float cn = sigf(gf) * cstate + sigf(gi) * tanhf(gg);
                float hn = sigf(go) * tanhf(cn);
                cstate = cn;
                float ho = hn + mt;

                d_mem[(size_t)(i + 1) * BH + off] = ho;

                float part = tanhf(ho) * wt2v;
#pragma unroll
                for (int o = 8; o > 0; o >>= 1) part += __shfl_xor_sync(0xffffffffu, part, o);
                if ((lane & 15) == 0)
                    atomicAdd(&d_s2[(bg * 16 + bl) * (T_ + 1) + (i + 1)], part);
            }

            gsync(i, NCTA);
        }
    } else {
        // ---------------- attention CTAs ----------------
        int b = (g - NGEMM) * 8 + wrp;
        for (int i = 0; i < T_; ++i) {
            int n = i + 1;
            float v[8];
            float mn = INFINITY;
#pragma unroll
            for (int r = 0; r < 8; r++) {
                int t = lane + 32 * r;
                if (t < n) {
                    float s = __ldcg(d_s2 + b * (T_ + 1) + t);
                    v[r] = s;
                    mn = fminf(mn, s);
                } else {
                    v[r] = -INFINITY;
                }
            }
#pragma unroll
            for (int o = 16; o > 0; o >>= 1) mn = fminf(mn, __shfl_xor_sync(0xffffffffu, mn, o));
            float topv[5]; int topt[5];
#pragma unroll
            for (int k5 = 0; k5 < 5; k5++) {
                float bv = -INFINITY; int bt = 1 << 30;
#pragma unroll
                for (int r = 0; r < 8; r++) {
                    int t = lane + 32 * r;
                    if (v[r] > bv) { bv = v[r]; bt = t; }
                }
#pragma unroll
                for (int o = 16; o > 0; o >>= 1) {
                    float ov = __shfl_xor_sync(0xffffffffu, bv, o);
                    int   ot = __shfl_xor_sync(0xffffffffu, bt, o);
                    if (ov > bv || (ov == bv && ot < bt)) { bv = ov; bt = ot; }
                }
                topv[k5] = bv; topt[k5] = bt;
                int rr = bt >> 5;
                if ((bt & 31) == lane && rr >= 0 && rr < 8) v[rr] = -INFINITY;
            }
            float delta = ((n <= 5) ? mn : topv[4]) + 1e-7f;
            float wk[5]; float sum = 0.f;
#pragma unroll
            for (int k5 = 0; k5 < 5; k5++) { wk[k5] = fmaxf(topv[k5] - delta, 0.f); sum += wk[k5]; }
            float inv = 1.f / (sum + 1e-7f);
            float acc[16];
#pragma unroll
            for (int r = 0; r < 16; r++) acc[r] = 0.f;
#pragma unroll
            for (int k5 = 0; k5 < 5; k5++) {
                float wv = wk[k5] * inv;
                if (wv > 0.f) {
                    const float* rowp = d_mem + (size_t)topt[k5] * BH + (size_t)b * H_;
#pragma unroll
                    for (int r = 0; r < 16; r++) acc[r] = fmaf(wv, __ldg(rowp + lane + 32 * r), acc[r]);
                }
            }
            float* mrow = d_mseq + (size_t)i * BH + (size_t)b * H_;
#pragma unroll
            for (int r = 0; r < 16; r++) mrow[lane + 32 * r] = acc[r];

            __threadfence();
            __syncthreads();
            if (tx == 0) atomicAdd(&d_aflag[i], 1u);

            gsync(i, NCTA);
        }
    }
}

// ---------------- K3: out = [h_seq | m_seq] @ fc_w^T + fc_b ----------------
__global__ void __launch_bounds__(256) fc_final_kernel(const float* __restrict__ fcw,
                                                       const float* __restrict__ fcb,
                                                       float* __restrict__ out) {
    __shared__ __align__(16) float a_s[16][64];
    __shared__ __align__(16) float b_s[16][64];
    int tx = threadIdx.x;
    int m0 = blockIdx.x * 64;
    int tm = tx & 15, tn = tx >> 4;
    float acc[4][4];
#pragma unroll
    for (int r = 0; r < 4; r++)
#pragma unroll
        for (int c = 0; c < 4; c++) acc[r][c] = 0.f;

    int row = tx >> 2, qd = tx & 3;
    int m = m0 + row, t = m >> 6, b = m & 63;
    for (int k0 = 0; k0 < 2 * H_; k0 += 16) {
        int k = k0 + qd * 4;
        const float* src = (k < H_)
            ? (d_mem + ((size_t)(t + 1) * B_ + b) * H_ + k)
            : (d_mseq + ((size_t)t * B_ + b) * H_ + (k - H_));
        float4 av = *(const float4*)src;
        float4 bv = *(const float4*)(fcw + (size_t)row * (2 * H_) + k);
        a_s[qd*4+0][row] = av.x; a_s[qd*4+1][row] = av.y; a_s[qd*4+2][row] = av.z; a_s[qd*4+3][row] = av.w;
        b_s[qd*4+0][row] = bv.x; b_s[qd*4+1][row] = bv.y; b_s[qd*4+2][row] = bv.z; b_s[qd*4+3][row] = bv.w;
        __syncthreads();
#pragma unroll
        for (int k2 = 0; k2 < 16; k2++) {
            float4 a = *(const float4*)&a_s[k2][tm * 4];
            float4 bb = *(const float4*)&b_s[k2][tn * 4];
            acc[0][0] = fmaf(a.x, bb.x, acc[0][0]); acc[0][1] = fmaf(a.x, bb.y, acc[0][1]);
            acc[0][2] = fmaf(a.x, bb.z, acc[0][2]); acc[0][3] = fmaf(a.x, bb.w, acc[0][3]);
            acc[1][0] = fmaf(a.y, bb.x, acc[1][0]); acc[1][1] = fmaf(a.y, bb.y, acc[1][1]);
            acc[1][2] = fmaf(a.y, bb.z, acc[1][2]); acc[1][3] = fmaf(a.y, bb.w, acc[1][3]);
            acc[2][0] = fmaf(a.z, bb.x, acc[2][0]); acc[2][1] = fmaf(a.z, bb.y, acc[2][1]);
            acc[2][2] = fmaf(a.z, bb.z, acc[2][2]); acc[2][3] = fmaf(a.z, bb.w, acc[2][3]);
            acc[3][0] = fmaf(a.w, bb.x, acc[3][0]); acc[3][1] = fmaf(a.w, bb.y, acc[3][1]);
            acc[3][2] = fmaf(a.w, bb.z, acc[3][2]); acc[3][3] = fmaf(a.w, bb.w, acc[3][3]);
        }
        __syncthreads();
    }
    float bias[4];
#pragma unroll
    for (int c = 0; c < 4; c++) bias[c] = __ldg(fcb + tn * 4 + c);
#pragma unroll
    for (int r = 0; r < 4; r++) {
        size_t mm = (size_t)(m0 + tm * 4 + r);
        float4 o;
        o.x = acc[r][0] + bias[0]; o.y = acc[r][1] + bias[1];
        o.z = acc[r][2] + bias[2]; o.w = acc[r][3] + bias[3];
        *(float4*)(out + mm * C_ + tn * 4) = o;
    }
}

// ---------------- launch ----------------
extern "C" void kernel_launch(void* const* d_in, const int* in_sizes, int n_in,
                              void* d_out, int out_size) {
    const float* x    = (const float*)d_in[0];
    const float* W_ih = (const float*)d_in[1];
    const float* W_hh = (const float*)d_in[2];
    const float* b_ih = (const float*)d_in[3];
    const float* b_hh = (const float*)d_in[4];
    const float* w_t  = (const float*)d_in[5];
    const float* fc_w = (const float*)d_in[6];
    const float* fc_b = (const float*)d_in[7];
    float* out = (float*)d_out;

    static int smem_set = 0;
    if (!smem_set) {
        cudaFuncSetAttribute(lstm_persistent,
                             cudaFuncAttributeMaxDynamicSharedMemorySize, SMEM_BYTES);
        smem_set = 1;
    }

    // ncu empirically profiles launch #4 -> place lstm_persistent there.
    reset_kernel<<<64, 512>>>();
    gemm_ih_kernel<<<dim3(G4H / 64, (T_ * B_) / 64), 256>>>(x, W_ih, b_ih, b_hh);
    noop_kernel<<<1, 1>>>();
    lstm_persistent<<<NCTA, 256, SMEM_BYTES>>>(W_hh, w_t);
    fc_final_kernel<<<(T_ * B_) / 64, 256>>>(fc_w, fc_b, out);
}